// round 15
// baseline (speedup 1.0000x reference)
#include <cuda_runtime.h>
#include <cuda_fp16.h>

#define BB 2
#define CC 64
#define NN 16384
#define KK 16
#define COUT 64

// Scratch (static device globals — no allocation allowed)
__device__ __half g_y1h[BB * NN * CC];   // (W1-W2)·x, node-major [b][n][o], fp16
__device__ __half g_y2h[BB * NN * CC];   // W2·x,      node-major [b][n][o], fp16
__device__ float  g_mean[BB * CC];       // per-batch channel means

// ---------------------------------------------------------------------------
// Kernel 1: per-(b,c) mean over nodes. 128 blocks x 256 threads.
// ---------------------------------------------------------------------------
__global__ void mean_kernel(const float* __restrict__ x) {
    int row = blockIdx.x;                       // b*64 + c
    const float* p = x + (size_t)row * NN;
    float s = 0.f;
    for (int i = threadIdx.x; i < NN; i += 256) s += p[i];
    for (int off = 16; off; off >>= 1) s += __shfl_down_sync(0xffffffffu, s, off);
    __shared__ float red[8];
    if ((threadIdx.x & 31) == 0) red[threadIdx.x >> 5] = s;
    __syncthreads();
    if (threadIdx.x < 8) {
        s = red[threadIdx.x];
        for (int off = 4; off; off >>= 1) s += __shfl_down_sync(0xffu, s, off);
        if (threadIdx.x == 0) g_mean[row] = s * (1.f / NN);
    }
}

// ---------------------------------------------------------------------------
// Kernel 2 (v3): y1/y2 GEMM, fp16 output, fma.rn.f32x2.
// R13 diagnosis: at grid 256 the gemm ran 1.73 blocks/SM — concurrency/
// balance bound, FMA2 couldn't help. 64-node tiles -> grid 512, 48KB static
// smem, 3 blocks/SM: 24 warps/SM of latency cover. Inner structure proven:
// 8 o-groups x 32 node-lanes, 2 nodes/thread, broadcast LDS.64 weight pairs,
// packed {y1,y2} accumulators.
// ---------------------------------------------------------------------------
__global__ void __launch_bounds__(256, 3) gemm_kernel(const float* __restrict__ x,
                                                      const float* __restrict__ W) {
    __shared__ float  xs[64 * 64];     // [c][node]        16KB
    __shared__ float2 wab[64 * 64];    // [o][c] {W1-W2,W2} 32KB

    int b  = blockIdx.x >> 8;          // 256 tiles per batch
    int n0 = (blockIdx.x & 255) << 6;
    int tid = threadIdx.x;

    for (int i = tid; i < 64 * 64; i += 256) {
        int o = i >> 6, c = i & 63;
        float w2 = W[o * 192 + 64 + c];
        wab[i] = make_float2(W[o * 192 + c] - w2, w2);
    }
    const float* xb = x + (size_t)b * CC * NN + n0;
    for (int i = tid; i < 64 * 64; i += 256) {
        int c = i >> 6, nl = i & 63;
        xs[i] = xb[(size_t)c * NN + nl];    // coalesced 64-float rows
    }
    __syncthreads();

    int nl = tid & 31;              // node lane (handles nl, nl+32)
    int o0 = (tid >> 5) * 8;        // 8 outputs per thread

    unsigned long long acc[2][8];   // packed {y1, y2} fp32 pairs
#pragma unroll
    for (int q = 0; q < 2; q++)
#pragma unroll
        for (int j = 0; j < 8; j++) acc[q][j] = 0ull;

    for (int c = 0; c < 64; c++) {
        unsigned long long xp[2];
#pragma unroll
        for (int q = 0; q < 2; q++) {
            float xv = xs[c * 64 + nl + q * 32];
            asm("mov.b64 %0, {%1, %1};" : "=l"(xp[q]) : "f"(xv));
        }
#pragma unroll
        for (int j = 0; j < 8; j++) {
            unsigned long long wp =
                *(const unsigned long long*)&wab[(o0 + j) * 64 + c];  // broadcast
#pragma unroll
            for (int q = 0; q < 2; q++)
                asm("fma.rn.f32x2 %0, %1, %2, %0;"
                    : "+l"(acc[q][j]) : "l"(wp), "l"(xp[q]));
        }
    }

#pragma unroll
    for (int q = 0; q < 2; q++) {
        float a1[8], a2[8];
#pragma unroll
        for (int j = 0; j < 8; j++)
            asm("mov.b64 {%0, %1}, %2;" : "=f"(a1[j]), "=f"(a2[j]) : "l"(acc[q][j]));
        size_t base = ((size_t)b * NN + n0 + nl + q * 32) * 64 + o0;
        uint4 v1, v2;
        __half2 p10 = __floats2half2_rn(a1[0], a1[1]);
        __half2 p11 = __floats2half2_rn(a1[2], a1[3]);
        __half2 p12 = __floats2half2_rn(a1[4], a1[5]);
        __half2 p13 = __floats2half2_rn(a1[6], a1[7]);
        v1.x = *(unsigned*)&p10; v1.y = *(unsigned*)&p11;
        v1.z = *(unsigned*)&p12; v1.w = *(unsigned*)&p13;
        __half2 p20 = __floats2half2_rn(a2[0], a2[1]);
        __half2 p21 = __floats2half2_rn(a2[2], a2[3]);
        __half2 p22 = __floats2half2_rn(a2[4], a2[5]);
        __half2 p23 = __floats2half2_rn(a2[6], a2[7]);
        v2.x = *(unsigned*)&p20; v2.y = *(unsigned*)&p21;
        v2.z = *(unsigned*)&p22; v2.w = *(unsigned*)&p23;
        *(uint4*)&g_y1h[base] = v1;      // o0 mult of 8 -> 16B aligned
        *(uint4*)&g_y2h[base] = v2;
    }
}

// ---------------------------------------------------------------------------
// Kernel 3: gather + max over K + (inlined dvec) + relu — fp16 tables,
// 32-node tiles, grid 1024. dvec (bias + W3·mean) computed per block in the
// prologue: 4 threads per output x 16 channels + quad shfl reduce (4M FMA
// total — noise), eliminating the separate dvec kernel + its launch bubble.
// ---------------------------------------------------------------------------
__global__ void __launch_bounds__(256, 6) gather_kernel(const int* __restrict__ ei,
                                                        const float* __restrict__ W,
                                                        const float* __restrict__ bias,
                                                        float* __restrict__ out) {
    __shared__ int   s_j0[32 * KK];
    __shared__ int   s_j1[32 * KK];
    __shared__ float s_d[64];
    __shared__ float s_out[64][34];     // [channel][node], padded

    int b   = blockIdx.x >> 9;          // 512 tiles per batch
    int n0  = (blockIdx.x & 511) << 5;
    int tid = threadIdx.x;

    // Inline dvec: d[o] = bias[o] + sum_c W3[o][c]*mean[b][c]
    {
        int o = tid >> 2, part = tid & 3;
        const float* mrow = g_mean + b * CC;
        float s = 0.f;
#pragma unroll
        for (int c8 = 0; c8 < 16; c8++) {
            int c = part * 16 + c8;
            s += __ldg(&W[o * 192 + 128 + c]) * mrow[c];
        }
        s += __shfl_xor_sync(0xffffffffu, s, 1);
        s += __shfl_xor_sync(0xffffffffu, s, 2);
        if (part == 0) s_d[o] = s + __ldg(&bias[o]);
    }

    const int* e0 = ei + ((size_t)b * NN + n0) * KK;            // neighbors (edge_index[0])
    const int* e1 = ei + ((size_t)(BB + b) * NN + n0) * KK;     // centers   (edge_index[1])
    for (int i = tid; i < 32 * KK; i += 256) {
        s_j0[i] = (e0[i] & (NN - 1)) << 4;   // uint2-row offset (row = 16 uint2)
        s_j1[i] = (e1[i] & (NN - 1)) << 4;
    }
    __syncthreads();

    int f4 = tid & 15;                  // which uint2 (4 halves) of the row
    int ng = tid >> 4;                  // node group 0..15 (2 nodes each)
    const uint2* y1 = (const uint2*)g_y1h + (size_t)b * NN * 16;
    const uint2* y2 = (const uint2*)g_y2h + (size_t)b * NN * 16;

    const __half2 NEG = __float2half2_rn(-60000.f);

#pragma unroll
    for (int nl = ng; nl < 32; nl += 16) {
        __half2 m0 = NEG, m1 = NEG;
        const int* pj1 = &s_j1[nl * KK];
        const int* pj0 = &s_j0[nl * KK];
#pragma unroll
        for (int k = 0; k < KK; k++) {
            uint2 r1 = __ldg(y1 + pj1[k] + f4);
            uint2 r0 = __ldg(y2 + pj0[k] + f4);
            __half2 a0 = *(__half2*)&r1.x, a1 = *(__half2*)&r1.y;
            __half2 c0 = *(__half2*)&r0.x, c1 = *(__half2*)&r0.y;
            m0 = __hmax2(m0, __hadd2(a0, c0));
            m1 = __hmax2(m1, __hadd2(a1, c1));
        }
        float2 f0 = __half22float2(m0);
        float2 f1 = __half22float2(m1);
        int o0 = f4 * 4;
        s_out[o0 + 0][nl] = f0.x;
        s_out[o0 + 1][nl] = f0.y;
        s_out[o0 + 2][nl] = f1.x;
        s_out[o0 + 3][nl] = f1.y;
    }
    __syncthreads();

    float* ob = out + (size_t)b * COUT * NN + n0;
    for (int i = tid; i < 64 * 8; i += 256) {        // 64 channels x 8 float4
        int o2 = i >> 3, q = i & 7;
        float d = s_d[o2];
        int nb = q * 4;
        float4 v;
        v.x = fmaxf(s_out[o2][nb + 0] + d, 0.f);
        v.y = fmaxf(s_out[o2][nb + 1] + d, 0.f);
        v.z = fmaxf(s_out[o2][nb + 2] + d, 0.f);
        v.w = fmaxf(s_out[o2][nb + 3] + d, 0.f);
        *(float4*)(ob + (size_t)o2 * NN + nb) = v;   // n0 mult of 32 -> 16B aligned
    }
}

// ---------------------------------------------------------------------------
extern "C" void kernel_launch(void* const* d_in, const int* in_sizes, int n_in,
                              void* d_out, int out_size) {
    const float* x    = (const float*)d_in[0];
    const int*   ei   = (const int*)d_in[1];
    const float* W    = (const float*)d_in[2];
    const float* bias = (const float*)d_in[3];
    float*       out  = (float*)d_out;

    mean_kernel<<<BB * CC, 256>>>(x);
    gemm_kernel<<<BB * (NN / 64), 256>>>(x, W);
    gather_kernel<<<BB * (NN / 32), 256>>>(ei, W, bias, out);
}